// round 5
// baseline (speedup 1.0000x reference)
#include <cuda_runtime.h>
#include <cuda_bf16.h>
#include <math.h>
#include <float.h>
#include <stdint.h>

#define B  4
#define C1 64
#define C2 256
#define C3 64
#define HW 9216
#define GOFF 97
#define HPAD 9410   // 97 guard + 9216 + 97 guard

// ---------------- scratch ----------------
__device__ float g_h[B*C2*HW];
__device__ float g_gl1[B*C1];
__device__ float g_dyn1[B*C2*C1];
__device__ float g_gl2[B*C2*9];
__device__ float g_outA[B*C2*9];
__device__ float g_ocp2[B*C3*9];
__device__ __align__(16) unsigned short g_hth[(size_t)B*HPAD*C2];  // bf16 hi, [b][row][c]
__device__ __align__(16) unsigned short g_htl[(size_t)B*HPAD*C2];  // bf16 lo
__device__ __align__(16) unsigned short g_w2h[B*9*C3*C2];          // [b][tap][o][c]
__device__ __align__(16) unsigned short g_w2l[B*9*C3*C2];

// ---------------- helpers ----------------
__device__ __forceinline__ uint32_t smem_u32(const void* p) {
    uint32_t a;
    asm("{ .reg .u64 t; cvta.to.shared.u64 t, %1; cvt.u32.u64 %0, t; }" : "=r"(a) : "l"(p));
    return a;
}
__device__ __forceinline__ void cp16(uint32_t dst, const void* src) {
    asm volatile("cp.async.cg.shared.global [%0], [%1], 16;" :: "r"(dst), "l"(src));
}
__device__ __forceinline__ void ldm4(uint32_t* r, uint32_t addr) {
    asm volatile("ldmatrix.sync.aligned.m8n8.x4.shared.b16 {%0,%1,%2,%3}, [%4];"
        : "=r"(r[0]), "=r"(r[1]), "=r"(r[2]), "=r"(r[3]) : "r"(addr));
}
__device__ __forceinline__ void mma16816(float* d, const uint32_t* a, uint32_t b0, uint32_t b1) {
    asm volatile("mma.sync.aligned.m16n8k16.row.col.f32.bf16.bf16.f32 "
        "{%0,%1,%2,%3}, {%4,%5,%6,%7}, {%8,%9}, {%0,%1,%2,%3};"
        : "+f"(d[0]), "+f"(d[1]), "+f"(d[2]), "+f"(d[3])
        : "r"(a[0]), "r"(a[1]), "r"(a[2]), "r"(a[3]), "r"(b0), "r"(b1));
}
__device__ __forceinline__ uint32_t sw128(uint32_t off) { return off ^ ((off >> 3) & 0x70); }

// ---------------- K0: zero guard rows ----------------
__global__ void k0_zero() {
    int i = blockIdx.x * 256 + threadIdx.x;       // B*194*128 u32
    if (i >= B * 194 * 128) return;
    int u = i & 127;
    int r = (i >> 7) % 194;
    int b = i / (194 * 128);
    int row = (r < 97) ? r : (GOFF + HW + (r - 97));
    size_t idx = ((size_t)b * HPAD + row) * 128 + u;
    ((uint32_t*)g_hth)[idx] = 0;
    ((uint32_t*)g_htl)[idx] = 0;
}

// ---------------- K1: gl1 ----------------
__global__ void k1_gl1(const float* __restrict__ x) {
    int bc = blockIdx.x;
    const float* p = x + (size_t)bc * HW;
    float m = -FLT_MAX;
    for (int l = threadIdx.x; l < HW; l += 256) m = fmaxf(m, p[l]);
    #pragma unroll
    for (int off = 16; off; off >>= 1) m = fmaxf(m, __shfl_xor_sync(0xffffffffu, m, off));
    __shared__ float sm[8];
    if ((threadIdx.x & 31) == 0) sm[threadIdx.x >> 5] = m;
    __syncthreads();
    if (threadIdx.x == 0) {
        float r = sm[0];
        #pragma unroll
        for (int i = 1; i < 8; i++) r = fmaxf(r, sm[i]);
        g_gl1[bc] = r;
    }
}

// ---------------- K2: fc1 dynamic weights ----------------
__global__ void k2_dyn1(const float* __restrict__ w1, const float* ce, const float* gd,
                        const float* gd2, const float* __restrict__ ci) {
    int b = blockIdx.x, t = threadIdx.x;
    __shared__ float s1[C1], sre[C1];
    float cev = ce[0], gdv = gd[0], gd2v = gd2[0];
    if (t < C1) {
        float r = fmaxf(g_gl1[b*C1 + t] * cev, 0.f);
        sre[t] = r; s1[t] = r * gdv;
    }
    __syncthreads();
    int p = t >> 5, o2 = t & 31;
    float v = 0.f;
    #pragma unroll
    for (int g = 0; g < 8; g++) v += sre[p*8+g] * ci[o2*8+g];
    float s2 = fmaxf(v, 0.f) * gd2v;
    for (int c = 0; c < C1; c++) {
        float s = s1[c] + s2;
        g_dyn1[(b*C2 + t)*C1 + c] = w1[t*C1 + c] / (1.f + expf(-s));
    }
}

// ---------------- K3: fc1 GEMM + GELU; writes g_h fp32 + transposed split bf16 ----------------
__global__ __launch_bounds__(256) void k3_fc1(const float* __restrict__ x) {
    __shared__ float sA[64*64];
    __shared__ float sB[64*64];
    int b = blockIdx.z, o0 = blockIdx.y * 64, l0 = blockIdx.x * 64;
    int t = threadIdx.x;
    for (int i = t; i < 4096; i += 256) {
        int o = i >> 6, c = i & 63;
        sA[i] = g_dyn1[(b*C2 + o0 + o)*C1 + c];
        sB[i] = x[(size_t)(b*C1 + o)*HW + l0 + c];
    }
    __syncthreads();
    int ty = t >> 4, tx = t & 15;
    float acc[4][4] = {};
    for (int c = 0; c < 64; c++) {
        float a[4], bb[4];
        #pragma unroll
        for (int i = 0; i < 4; i++) a[i]  = sA[(ty + 16*i)*64 + c];
        #pragma unroll
        for (int j = 0; j < 4; j++) bb[j] = sB[c*64 + tx + 16*j];
        #pragma unroll
        for (int i = 0; i < 4; i++)
            #pragma unroll
            for (int j = 0; j < 4; j++) acc[i][j] += a[i] * bb[j];
    }
    __syncthreads();
    unsigned short* sh16 = (unsigned short*)sA;       // [l_local][o_local] hi
    unsigned short* sl16 = (unsigned short*)sB;       // lo
    #pragma unroll
    for (int i = 0; i < 4; i++)
        #pragma unroll
        for (int j = 0; j < 4; j++) {
            float v = acc[i][j];
            v = 0.5f * v * (1.f + erff(v * 0.70710678118654752f));
            int ll = tx + 16*j, oo = ty + 16*i;
            g_h[(size_t)(b*C2 + o0 + oo)*HW + l0 + ll] = v;
            __nv_bfloat16 hb = __float2bfloat16(v);
            float hf = __bfloat162float(hb);
            __nv_bfloat16 lb = __float2bfloat16(v - hf);
            sh16[ll*64 + oo] = __bfloat16_as_ushort(hb);
            sl16[ll*64 + oo] = __bfloat16_as_ushort(lb);
        }
    __syncthreads();
    const uint4* s4h = (const uint4*)sh16;
    const uint4* s4l = (const uint4*)sl16;
    #pragma unroll
    for (int i = t; i < 512; i += 256) {
        int r = i >> 3, q = i & 7;
        size_t dst = ((size_t)b*HPAD + GOFF + l0 + r) * 32 + (o0 >> 3) + q;
        ((uint4*)g_hth)[dst] = s4h[i];
        ((uint4*)g_htl)[dst] = s4l[i];
    }
}

// ---------------- K4: gl2 = 3x3 adaptive max pool ----------------
__global__ void k4_gl2() {
    int c = blockIdx.x, b = blockIdx.y;
    const float* p = g_h + (size_t)(b * C2 + c) * HW + threadIdx.x;
    #pragma unroll
    for (int band = 0; band < 3; band++) {
        const float* q = p + band * 32 * 96;
        float mm = -FLT_MAX;
        #pragma unroll 8
        for (int y = 0; y < 32; y++) mm = fmaxf(mm, q[y * 96]);
        #pragma unroll
        for (int off = 16; off; off >>= 1) mm = fmaxf(mm, __shfl_xor_sync(0xffffffffu, mm, off));
        if ((threadIdx.x & 31) == 0)
            g_gl2[(b * C2 + c) * 9 + band * 3 + (threadIdx.x >> 5)] = mm;
    }
}

// ---------------- K5a: fc2 gating scalars ----------------
__global__ void k5a(const float* __restrict__ ce_w, const float* __restrict__ gd_w,
                    const float* __restrict__ gd2_w, const float* __restrict__ ci_w) {
    int b = blockIdx.x, t = threadIdx.x;
    __shared__ float sre[C2][5];
    {
        float glv[9];
        #pragma unroll
        for (int k = 0; k < 9; k++) glv[k] = g_gl2[(b*C2 + t)*9 + k];
        float rc[5];
        #pragma unroll
        for (int n = 0; n < 5; n++) {
            float v = 0.f;
            #pragma unroll
            for (int k = 0; k < 9; k++) v += glv[k] * ce_w[n*9 + k];
            rc[n] = fmaxf(v, 0.f);
            sre[t][n] = rc[n];
        }
        #pragma unroll
        for (int k = 0; k < 9; k++) {
            float v = 0.f;
            #pragma unroll
            for (int n = 0; n < 5; n++) v += rc[n] * gd_w[k*5 + n];
            g_outA[(b*C2 + t)*9 + k] = v;
        }
    }
    __syncthreads();
    if (t < C3) {
        int p = t >> 1, o2 = t & 1;
        float v[5];
        #pragma unroll
        for (int n = 0; n < 5; n++) {
            float s = 0.f;
            #pragma unroll
            for (int g = 0; g < 8; g++) s += sre[p*8+g][n] * ci_w[o2*8 + g];
            v[n] = fmaxf(s, 0.f);
        }
        #pragma unroll
        for (int k = 0; k < 9; k++) {
            float s = 0.f;
            #pragma unroll
            for (int n = 0; n < 5; n++) s += v[n] * gd2_w[k*5 + n];
            g_ocp2[(b*C3 + t)*9 + k] = s;
        }
    }
}

// ---------------- K5b: split dynamic fc2 weights into bf16 hi/lo, [b][tap][o][c] ----------------
__global__ void k5b(const float* __restrict__ w2) {
    int idx = blockIdx.x * 256 + threadIdx.x;       // ((b*9+k)*64+o)*256 + c
    int c = idx & 255;
    int o = (idx >> 8) & 63;
    int t2 = idx >> 14;
    int k = t2 % 9, b = t2 / 9;
    float s = g_outA[(b*C2 + c)*9 + k] + g_ocp2[(b*C3 + o)*9 + k];
    float w = w2[(o*C2 + c)*9 + k] / (1.f + expf(-s));
    __nv_bfloat16 hb = __float2bfloat16(w);
    float hf = __bfloat162float(hb);
    __nv_bfloat16 lb = __float2bfloat16(w - hf);
    g_w2h[idx] = __bfloat16_as_ushort(hb);
    g_w2l[idx] = __bfloat16_as_ushort(lb);
}

// ---------------- K6: fc2 via mma.sync bf16 split-2, shift-based implicit im2col ----------------
// smem carve: Ah[0,16K) Al[16K,32K) Bh[32K,40K) Bl[40K,48K); epilogue reuses [0,32K) as float D
__global__ __launch_bounds__(256, 2) void k6_fc2(float* __restrict__ out) {
    __shared__ __align__(128) unsigned char smem_all[49152];
    uint32_t aAh = smem_u32(smem_all);
    uint32_t aAl = aAh + 16384;
    uint32_t aBh = aAh + 32768;
    uint32_t aBl = aAh + 40960;

    int tile = blockIdx.x, b = blockIdx.y;
    int l0 = tile * 128;
    int t = threadIdx.x;
    int w = t >> 5, lane = t & 31;

    float acc[8][4];
    #pragma unroll
    for (int i = 0; i < 8; i++)
        #pragma unroll
        for (int j = 0; j < 4; j++) acc[i][j] = 0.f;

    const unsigned short* hh = g_hth + (size_t)b * HPAD * 256 + (size_t)GOFF * 256;
    const unsigned short* hl = g_htl + (size_t)b * HPAD * 256 + (size_t)GOFF * 256;

    for (int step = 0; step < 36; step++) {
        int cb = step / 9, tap = step - cb * 9;
        int dy = tap / 3, dx = tap - dy * 3;
        int rshift = l0 + dy * 96 + dx - 97;           // guard rows make all indices valid

        // stage A: 128 rows x 64 c (hi+lo), 16B chunks, swizzled
        #pragma unroll
        for (int j = 0; j < 4; j++) {
            int i = t + j * 256;                        // 0..1023
            int row = i >> 3, u = i & 7;
            uint32_t sw = sw128((uint32_t)(row * 128 + u * 16));
            size_t so = (size_t)(rshift + row) * 256 + cb * 64 + u * 8;
            cp16(aAh + sw, hh + so);
            cp16(aAl + sw, hl + so);
        }
        // stage B: 64 rows (o) x 64 c (hi+lo)
        const unsigned short* wbh = g_w2h + ((size_t)(b*9 + tap) * 64) * 256 + cb * 64;
        const unsigned short* wbl = g_w2l + ((size_t)(b*9 + tap) * 64) * 256 + cb * 64;
        #pragma unroll
        for (int j = 0; j < 2; j++) {
            int i = t + j * 256;                        // 0..511
            int row = i >> 3, u = i & 7;
            uint32_t sw = sw128((uint32_t)(row * 128 + u * 16));
            cp16(aBh + sw, wbh + (size_t)row * 256 + u * 8);
            cp16(aBl + sw, wbl + (size_t)row * 256 + u * 8);
        }
        asm volatile("cp.async.commit_group;" ::: "memory");
        asm volatile("cp.async.wait_group 0;" ::: "memory");
        __syncthreads();

        #pragma unroll
        for (int kk = 0; kk < 4; kk++) {
            uint32_t aoff = sw128((uint32_t)((16*w + (lane & 15)) * 128 + kk * 32 + (lane >> 4) * 16));
            uint32_t ah[4], al[4];
            ldm4(ah, aAh + aoff);
            ldm4(al, aAl + aoff);
            #pragma unroll
            for (int p = 0; p < 4; p++) {
                uint32_t boff = sw128((uint32_t)((p*16 + (lane & 15)) * 128 + kk * 32 + (lane >> 4) * 16));
                uint32_t bh[4], bl[4];
                ldm4(bh, aBh + boff);
                ldm4(bl, aBl + boff);
                mma16816(acc[2*p],   ah, bh[0], bh[2]);
                mma16816(acc[2*p+1], ah, bh[1], bh[3]);
                mma16816(acc[2*p],   ah, bl[0], bl[2]);
                mma16816(acc[2*p+1], ah, bl[1], bl[3]);
                mma16816(acc[2*p],   al, bh[0], bh[2]);
                mma16816(acc[2*p+1], al, bh[1], bh[3]);
            }
        }
        __syncthreads();
    }

    // epilogue: frag -> smem [o][l] -> gmem
    float* sD = (float*)smem_all;                      // 64 x 128 floats
    int r = lane >> 2, c2 = (lane & 3) * 2;
    #pragma unroll
    for (int p = 0; p < 8; p++) {
        int o = p * 8 + c2;
        sD[(o    ) * 128 + 16*w + r    ] = acc[p][0];
        sD[(o + 1) * 128 + 16*w + r    ] = acc[p][1];
        sD[(o    ) * 128 + 16*w + r + 8] = acc[p][2];
        sD[(o + 1) * 128 + 16*w + r + 8] = acc[p][3];
    }
    __syncthreads();
    float* ob = out + (size_t)b * C3 * HW + l0;
    #pragma unroll 4
    for (int i = t; i < 8192; i += 256)
        ob[(size_t)(i >> 7) * HW + (i & 127)] = sD[i];
}

// ---------------- K7: exact recompute of x=0 / x=95 edge columns ----------------
__global__ void k7_edges(float* __restrict__ out) {
    int y = blockIdx.x, side = blockIdx.y, b = blockIdx.z;
    int x = side ? 95 : 0;
    int t = threadIdx.x;                      // t = o (64)
    __shared__ float sH[9][256];
    for (int tap = 0; tap < 9; tap++) {
        int dy = tap / 3, dx = tap % 3;
        int yy = y + dy - 1, xx = x + dx - 1;
        bool valid = ((unsigned)yy < 96u) && ((unsigned)xx < 96u);
        size_t rb = ((size_t)b * HPAD + GOFF + yy * 96 + xx) * 128;
        #pragma unroll
        for (int j = 0; j < 2; j++) {
            int ci = t + j * 64;
            float v0 = 0.f, v1 = 0.f;
            if (valid) {
                uint32_t uh = ((const uint32_t*)g_hth)[rb + ci];
                uint32_t ul = ((const uint32_t*)g_htl)[rb + ci];
                v0 = __bfloat162float(__ushort_as_bfloat16((unsigned short)(uh & 0xFFFF)))
                   + __bfloat162float(__ushort_as_bfloat16((unsigned short)(ul & 0xFFFF)));
                v1 = __bfloat162float(__ushort_as_bfloat16((unsigned short)(uh >> 16)))
                   + __bfloat162float(__ushort_as_bfloat16((unsigned short)(ul >> 16)));
            }
            sH[tap][2*ci]     = v0;
            sH[tap][2*ci + 1] = v1;
        }
    }
    __syncthreads();
    float acc = 0.f;
    for (int tap = 0; tap < 9; tap++) {
        const uint32_t* wh = (const uint32_t*)g_w2h + ((size_t)((b*9 + tap)*64 + t)) * 128;
        const uint32_t* wl = (const uint32_t*)g_w2l + ((size_t)((b*9 + tap)*64 + t)) * 128;
        #pragma unroll 4
        for (int ci = 0; ci < 128; ci++) {
            uint32_t uh = wh[ci], ul = wl[ci];
            float w0 = __bfloat162float(__ushort_as_bfloat16((unsigned short)(uh & 0xFFFF)))
                     + __bfloat162float(__ushort_as_bfloat16((unsigned short)(ul & 0xFFFF)));
            float w1 = __bfloat162float(__ushort_as_bfloat16((unsigned short)(uh >> 16)))
                     + __bfloat162float(__ushort_as_bfloat16((unsigned short)(ul >> 16)));
            acc += sH[tap][2*ci] * w0 + sH[tap][2*ci + 1] * w1;
        }
    }
    out[((size_t)b * C3 + t) * HW + y * 96 + x] = acc;
}

// ---------------- launch ----------------
extern "C" void kernel_launch(void* const* d_in, const int* in_sizes, int n_in,
                              void* d_out, int out_size) {
    const float* x     = (const float*)d_in[0];
    const float* w1    = (const float*)d_in[1];
    const float* f1ce  = (const float*)d_in[2];
    const float* f1gd  = (const float*)d_in[3];
    const float* f1gd2 = (const float*)d_in[4];
    const float* f1ci  = (const float*)d_in[5];
    const float* w2    = (const float*)d_in[6];
    const float* f2ce  = (const float*)d_in[7];
    const float* f2gd  = (const float*)d_in[8];
    const float* f2gd2 = (const float*)d_in[9];
    const float* f2ci  = (const float*)d_in[10];
    float* out = (float*)d_out;

    k0_zero<<<(B*194*128 + 255)/256, 256>>>();
    k1_gl1<<<B*C1, 256>>>(x);
    k2_dyn1<<<B, 256>>>(w1, f1ce, f1gd, f1gd2, f1ci);
    k3_fc1<<<dim3(HW/64, C2/64, B), 256>>>(x);
    k4_gl2<<<dim3(C2, B), 96>>>();
    k5a<<<B, 256>>>(f2ce, f2gd, f2gd2, f2ci);
    k5b<<<(B*9*C3*C2)/256, 256>>>(w2);
    k6_fc2<<<dim3(72, B), 256>>>(out);
    k7_edges<<<dim3(96, 2, B), 64>>>(out);
}

// round 6
// speedup vs baseline: 1.4977x; 1.4977x over previous
#include <cuda_runtime.h>
#include <cuda_bf16.h>
#include <math.h>
#include <float.h>
#include <stdint.h>

#define B  4
#define C1 64
#define C2 256
#define C3 64
#define HW 9216
#define GOFF 97
#define HPAD 9410   // 97 guard + 9216 + 97 guard

// ---------------- scratch ----------------
__device__ float g_h[B*C2*HW];
__device__ float g_gl1[B*C1];
__device__ float g_dyn1[B*C2*C1];
__device__ float g_gl2[B*C2*9];
__device__ float g_outA[B*C2*9];
__device__ float g_ocp2[B*C3*9];
__device__ __align__(16) unsigned short g_hth[(size_t)B*HPAD*C2];  // bf16 hi, [b][row][c]
__device__ __align__(16) unsigned short g_htl[(size_t)B*HPAD*C2];  // bf16 lo
__device__ __align__(16) unsigned short g_w2h[B*9*C3*C2];          // [b][tap][o][c]
__device__ __align__(16) unsigned short g_w2l[B*9*C3*C2];
__device__ __align__(16) float g_w2f[B*9*C3*C2];                   // fp32 combined (for edges)

// ---------------- helpers ----------------
__device__ __forceinline__ uint32_t smem_u32(const void* p) {
    uint32_t a;
    asm("{ .reg .u64 t; cvta.to.shared.u64 t, %1; cvt.u32.u64 %0, t; }" : "=r"(a) : "l"(p));
    return a;
}
__device__ __forceinline__ void cp16(uint32_t dst, const void* src) {
    asm volatile("cp.async.cg.shared.global [%0], [%1], 16;" :: "r"(dst), "l"(src));
}
__device__ __forceinline__ void ldm4(uint32_t* r, uint32_t addr) {
    asm volatile("ldmatrix.sync.aligned.m8n8.x4.shared.b16 {%0,%1,%2,%3}, [%4];"
        : "=r"(r[0]), "=r"(r[1]), "=r"(r[2]), "=r"(r[3]) : "r"(addr));
}
__device__ __forceinline__ void mma16816(float* d, const uint32_t* a, uint32_t b0, uint32_t b1) {
    asm volatile("mma.sync.aligned.m16n8k16.row.col.f32.bf16.bf16.f32 "
        "{%0,%1,%2,%3}, {%4,%5,%6,%7}, {%8,%9}, {%0,%1,%2,%3};"
        : "+f"(d[0]), "+f"(d[1]), "+f"(d[2]), "+f"(d[3])
        : "r"(a[0]), "r"(a[1]), "r"(a[2]), "r"(a[3]), "r"(b0), "r"(b1));
}
__device__ __forceinline__ uint32_t sw128(uint32_t off) { return off ^ ((off >> 3) & 0x70); }
__device__ __forceinline__ void rec2(uint32_t uh, uint32_t ul, float& v0, float& v1) {
    v0 = __bfloat162float(__ushort_as_bfloat16((unsigned short)(uh & 0xFFFF)))
       + __bfloat162float(__ushort_as_bfloat16((unsigned short)(ul & 0xFFFF)));
    v1 = __bfloat162float(__ushort_as_bfloat16((unsigned short)(uh >> 16)))
       + __bfloat162float(__ushort_as_bfloat16((unsigned short)(ul >> 16)));
}

// ---------------- K0: zero guard rows ----------------
__global__ void k0_zero() {
    int i = blockIdx.x * 256 + threadIdx.x;       // B*194*128 u32
    if (i >= B * 194 * 128) return;
    int u = i & 127;
    int r = (i >> 7) % 194;
    int b = i / (194 * 128);
    int row = (r < 97) ? r : (GOFF + HW + (r - 97));
    size_t idx = ((size_t)b * HPAD + row) * 128 + u;
    ((uint32_t*)g_hth)[idx] = 0;
    ((uint32_t*)g_htl)[idx] = 0;
}

// ---------------- K1: gl1 ----------------
__global__ void k1_gl1(const float* __restrict__ x) {
    int bc = blockIdx.x;
    const float* p = x + (size_t)bc * HW;
    float m = -FLT_MAX;
    for (int l = threadIdx.x; l < HW; l += 256) m = fmaxf(m, p[l]);
    #pragma unroll
    for (int off = 16; off; off >>= 1) m = fmaxf(m, __shfl_xor_sync(0xffffffffu, m, off));
    __shared__ float sm[8];
    if ((threadIdx.x & 31) == 0) sm[threadIdx.x >> 5] = m;
    __syncthreads();
    if (threadIdx.x == 0) {
        float r = sm[0];
        #pragma unroll
        for (int i = 1; i < 8; i++) r = fmaxf(r, sm[i]);
        g_gl1[bc] = r;
    }
}

// ---------------- K2: fc1 dynamic weights ----------------
__global__ void k2_dyn1(const float* __restrict__ w1, const float* ce, const float* gd,
                        const float* gd2, const float* __restrict__ ci) {
    int b = blockIdx.x, t = threadIdx.x;
    __shared__ float s1[C1], sre[C1];
    float cev = ce[0], gdv = gd[0], gd2v = gd2[0];
    if (t < C1) {
        float r = fmaxf(g_gl1[b*C1 + t] * cev, 0.f);
        sre[t] = r; s1[t] = r * gdv;
    }
    __syncthreads();
    int p = t >> 5, o2 = t & 31;
    float v = 0.f;
    #pragma unroll
    for (int g = 0; g < 8; g++) v += sre[p*8+g] * ci[o2*8+g];
    float s2 = fmaxf(v, 0.f) * gd2v;
    for (int c = 0; c < C1; c++) {
        float s = s1[c] + s2;
        g_dyn1[(b*C2 + t)*C1 + c] = w1[t*C1 + c] / (1.f + expf(-s));
    }
}

// ---------------- K3: fc1 GEMM + GELU; fp32 g_h + transposed split bf16 (conflict-free pack) ----------------
__global__ __launch_bounds__(256) void k3_fc1(const float* __restrict__ x) {
    __shared__ __align__(16) float sA[64*64];
    __shared__ __align__(16) float sB[64*64];
    int b = blockIdx.z, o0 = blockIdx.y * 64, l0 = blockIdx.x * 64;
    int t = threadIdx.x;
    for (int i = t; i < 4096; i += 256) {
        int o = i >> 6, c = i & 63;
        sA[i] = g_dyn1[(b*C2 + o0 + o)*C1 + c];
        sB[i] = x[(size_t)(b*C1 + o)*HW + l0 + c];
    }
    __syncthreads();
    int ty = t >> 4, tx = t & 15;
    float acc[4][4] = {};
    for (int c = 0; c < 64; c++) {
        float a[4], bb[4];
        #pragma unroll
        for (int i = 0; i < 4; i++) a[i]  = sA[(ty + 16*i)*64 + c];
        #pragma unroll
        for (int j = 0; j < 4; j++) bb[j] = sB[c*64 + tx + 16*j];
        #pragma unroll
        for (int i = 0; i < 4; i++)
            #pragma unroll
            for (int j = 0; j < 4; j++) acc[i][j] += a[i] * bb[j];
    }
    __syncthreads();
    unsigned short* sh16 = (unsigned short*)sA;       // [ll][oo] stride 68 (conflict-free)
    unsigned short* sl16 = (unsigned short*)sB;
    #pragma unroll
    for (int i = 0; i < 4; i++)
        #pragma unroll
        for (int j = 0; j < 4; j++) {
            float v = acc[i][j];
            v = 0.5f * v * (1.f + erff(v * 0.70710678118654752f));
            int ll = tx + 16*j, oo = ty + 16*i;
            g_h[(size_t)(b*C2 + o0 + oo)*HW + l0 + ll] = v;
            __nv_bfloat16 hb = __float2bfloat16(v);
            float hf = __bfloat162float(hb);
            __nv_bfloat16 lb = __float2bfloat16(v - hf);
            sh16[ll*68 + oo] = __bfloat16_as_ushort(hb);
            sl16[ll*68 + oo] = __bfloat16_as_ushort(lb);
        }
    __syncthreads();
    #pragma unroll
    for (int i = t; i < 1024; i += 256) {
        int r = i >> 4, q = i & 15;
        uint2 vh = *(const uint2*)&sh16[r*68 + q*4];
        uint2 vl = *(const uint2*)&sl16[r*68 + q*4];
        size_t dst = ((size_t)b*HPAD + GOFF + l0 + r) * 64 + (o0 >> 2) + q;
        ((uint2*)g_hth)[dst] = vh;
        ((uint2*)g_htl)[dst] = vl;
    }
}

// ---------------- K4: gl2 = 3x3 adaptive max pool ----------------
__global__ void k4_gl2() {
    int c = blockIdx.x, b = blockIdx.y;
    const float* p = g_h + (size_t)(b * C2 + c) * HW + threadIdx.x;
    #pragma unroll
    for (int band = 0; band < 3; band++) {
        const float* q = p + band * 32 * 96;
        float mm = -FLT_MAX;
        #pragma unroll 8
        for (int y = 0; y < 32; y++) mm = fmaxf(mm, q[y * 96]);
        #pragma unroll
        for (int off = 16; off; off >>= 1) mm = fmaxf(mm, __shfl_xor_sync(0xffffffffu, mm, off));
        if ((threadIdx.x & 31) == 0)
            g_gl2[(b * C2 + c) * 9 + band * 3 + (threadIdx.x >> 5)] = mm;
    }
}

// ---------------- K5a: fc2 gating scalars ----------------
__global__ void k5a(const float* __restrict__ ce_w, const float* __restrict__ gd_w,
                    const float* __restrict__ gd2_w, const float* __restrict__ ci_w) {
    int b = blockIdx.x, t = threadIdx.x;
    __shared__ float sre[C2][5];
    {
        float glv[9];
        #pragma unroll
        for (int k = 0; k < 9; k++) glv[k] = g_gl2[(b*C2 + t)*9 + k];
        float rc[5];
        #pragma unroll
        for (int n = 0; n < 5; n++) {
            float v = 0.f;
            #pragma unroll
            for (int k = 0; k < 9; k++) v += glv[k] * ce_w[n*9 + k];
            rc[n] = fmaxf(v, 0.f);
            sre[t][n] = rc[n];
        }
        #pragma unroll
        for (int k = 0; k < 9; k++) {
            float v = 0.f;
            #pragma unroll
            for (int n = 0; n < 5; n++) v += rc[n] * gd_w[k*5 + n];
            g_outA[(b*C2 + t)*9 + k] = v;
        }
    }
    __syncthreads();
    if (t < C3) {
        int p = t >> 1, o2 = t & 1;
        float v[5];
        #pragma unroll
        for (int n = 0; n < 5; n++) {
            float s = 0.f;
            #pragma unroll
            for (int g = 0; g < 8; g++) s += sre[p*8+g][n] * ci_w[o2*8 + g];
            v[n] = fmaxf(s, 0.f);
        }
        #pragma unroll
        for (int k = 0; k < 9; k++) {
            float s = 0.f;
            #pragma unroll
            for (int n = 0; n < 5; n++) s += v[n] * gd2_w[k*5 + n];
            g_ocp2[(b*C3 + t)*9 + k] = s;
        }
    }
}

// ---------------- K5b: split weights (bf16 hi/lo) + fp32 combined, [b][tap][o][c] ----------------
__global__ void k5b(const float* __restrict__ w2) {
    int idx = blockIdx.x * 256 + threadIdx.x;       // ((b*9+k)*64+o)*256 + c
    int c = idx & 255;
    int o = (idx >> 8) & 63;
    int t2 = idx >> 14;
    int k = t2 % 9, b = t2 / 9;
    float s = g_outA[(b*C2 + c)*9 + k] + g_ocp2[(b*C3 + o)*9 + k];
    float w = w2[(o*C2 + c)*9 + k] / (1.f + expf(-s));
    __nv_bfloat16 hb = __float2bfloat16(w);
    float hf = __bfloat162float(hb);
    __nv_bfloat16 lb = __float2bfloat16(w - hf);
    g_w2h[idx] = __bfloat16_as_ushort(hb);
    g_w2l[idx] = __bfloat16_as_ushort(lb);
    g_w2f[idx] = __bfloat162float(hb) + __bfloat162float(lb);
}

// ---------------- K6: fc2 via mma.sync bf16 split-2, double-buffered staging ----------------
__device__ __forceinline__ void stage6(uint32_t base, const unsigned short* hh,
        const unsigned short* hl, int b, int l0, int step, int t) {
    int cb = step / 9, tap = step - cb * 9;
    int dy = tap / 3, dx = tap - dy * 3;
    int rshift = l0 + dy * 96 + dx - 97;
    #pragma unroll
    for (int j = 0; j < 4; j++) {
        int i = t + j * 256;
        int row = i >> 3, u = i & 7;
        uint32_t sw = sw128((uint32_t)(row * 128 + u * 16));
        size_t so = (size_t)(rshift + row) * 256 + cb * 64 + u * 8;
        cp16(base + sw, hh + so);
        cp16(base + 16384 + sw, hl + so);
    }
    const unsigned short* wbh = g_w2h + ((size_t)(b * 9 + tap) * 64) * 256 + cb * 64;
    const unsigned short* wbl = g_w2l + ((size_t)(b * 9 + tap) * 64) * 256 + cb * 64;
    #pragma unroll
    for (int j = 0; j < 2; j++) {
        int i = t + j * 256;
        int row = i >> 3, u = i & 7;
        uint32_t sw = sw128((uint32_t)(row * 128 + u * 16));
        cp16(base + 32768 + sw, wbh + (size_t)row * 256 + u * 8);
        cp16(base + 40960 + sw, wbl + (size_t)row * 256 + u * 8);
    }
}

__global__ __launch_bounds__(256, 2) void k6_fc2(float* __restrict__ out) {
    extern __shared__ __align__(128) unsigned char sdy[];
    uint32_t base0 = smem_u32(sdy);
    int tile = blockIdx.x, b = blockIdx.y;
    int l0 = tile * 128, t = threadIdx.x;
    int w = t >> 5, lane = t & 31;

    const unsigned short* hh = g_hth + ((size_t)b * HPAD + GOFF) * 256;
    const unsigned short* hl = g_htl + ((size_t)b * HPAD + GOFF) * 256;

    float acc[8][4];
    #pragma unroll
    for (int i = 0; i < 8; i++)
        #pragma unroll
        for (int j = 0; j < 4; j++) acc[i][j] = 0.f;

    stage6(base0, hh, hl, b, l0, 0, t);
    asm volatile("cp.async.commit_group;" ::: "memory");

    for (int step = 0; step < 36; step++) {
        if (step < 35) {
            stage6(base0 + ((step + 1) & 1) * 49152, hh, hl, b, l0, step + 1, t);
            asm volatile("cp.async.commit_group;" ::: "memory");
            asm volatile("cp.async.wait_group 1;" ::: "memory");
        } else {
            asm volatile("cp.async.wait_group 0;" ::: "memory");
        }
        __syncthreads();
        uint32_t aAh = base0 + (step & 1) * 49152;
        uint32_t aAl = aAh + 16384, aBh = aAh + 32768, aBl = aAh + 40960;
        #pragma unroll
        for (int kk = 0; kk < 4; kk++) {
            uint32_t aoff = sw128((uint32_t)((16*w + (lane & 15)) * 128 + kk * 32 + (lane >> 4) * 16));
            uint32_t ah[4], al[4];
            ldm4(ah, aAh + aoff);
            ldm4(al, aAl + aoff);
            #pragma unroll
            for (int p = 0; p < 4; p++) {
                uint32_t boff = sw128((uint32_t)((p*16 + (lane & 15)) * 128 + kk * 32 + (lane >> 4) * 16));
                uint32_t bh[4], bl[4];
                ldm4(bh, aBh + boff);
                ldm4(bl, aBl + boff);
                mma16816(acc[2*p],   ah, bh[0], bh[2]);
                mma16816(acc[2*p+1], ah, bh[1], bh[3]);
                mma16816(acc[2*p],   ah, bl[0], bl[2]);
                mma16816(acc[2*p+1], ah, bl[1], bl[3]);
                mma16816(acc[2*p],   al, bh[0], bh[2]);
                mma16816(acc[2*p+1], al, bh[1], bh[3]);
            }
        }
        __syncthreads();
    }

    // epilogue: frag -> smem [o][l] -> gmem
    float* sD = (float*)sdy;                           // 64 x 128 floats (32KB)
    int r = lane >> 2, c2 = (lane & 3) * 2;
    #pragma unroll
    for (int p = 0; p < 8; p++) {
        int o = p * 8 + c2;
        sD[(o    ) * 128 + 16*w + r    ] = acc[p][0];
        sD[(o + 1) * 128 + 16*w + r    ] = acc[p][1];
        sD[(o    ) * 128 + 16*w + r + 8] = acc[p][2];
        sD[(o + 1) * 128 + 16*w + r + 8] = acc[p][3];
    }
    __syncthreads();
    float* ob = out + (size_t)b * C3 * HW + l0;
    #pragma unroll 4
    for (int i = t; i < 8192; i += 256)
        ob[(size_t)(i >> 7) * HW + (i & 127)] = sD[i];
}

// ---------------- K7: exact edge columns; one warp per (y, side, b); coalesced ----------------
__global__ void k7_edges(float* __restrict__ out) {
    int y = blockIdx.x, side = blockIdx.y, b = blockIdx.z;
    int lane = threadIdx.x;                       // 32 lanes = c dimension (8 c each)
    int xbase = side ? 94 : 0, x = side ? 95 : 0;
    int dx0 = side ? 0 : 1;                       // valid dx = dx0, dx0+1

    float hv[6][8];
    #pragma unroll
    for (int dy = 0; dy < 3; dy++)
        #pragma unroll
        for (int xxi = 0; xxi < 2; xxi++) {
            int l = (y + dy - 1) * 96 + xbase + xxi;   // guards cover OOB rows
            size_t ro = ((size_t)b * HPAD + GOFF + l) * 128 + lane * 4;
            uint4 uh = *(const uint4*)((const uint32_t*)g_hth + ro);
            uint4 ul = *(const uint4*)((const uint32_t*)g_htl + ro);
            float* hd = hv[dy*2 + xxi];
            rec2(uh.x, ul.x, hd[0], hd[1]);
            rec2(uh.y, ul.y, hd[2], hd[3]);
            rec2(uh.z, ul.z, hd[4], hd[5]);
            rec2(uh.w, ul.w, hd[6], hd[7]);
        }

    for (int o = 0; o < 64; o++) {
        float acc = 0.f;
        #pragma unroll
        for (int dy = 0; dy < 3; dy++)
            #pragma unroll
            for (int dxi = 0; dxi < 2; dxi++) {
                int tap = dy*3 + dx0 + dxi;
                const float* wf = g_w2f + ((size_t)((b*9 + tap)*64 + o))*256 + lane*8;
                float4 w0 = ((const float4*)wf)[0];
                float4 w1 = ((const float4*)wf)[1];
                const float* hd = hv[dy*2 + dxi];
                acc += hd[0]*w0.x + hd[1]*w0.y + hd[2]*w0.z + hd[3]*w0.w
                     + hd[4]*w1.x + hd[5]*w1.y + hd[6]*w1.z + hd[7]*w1.w;
            }
        #pragma unroll
        for (int off = 16; off; off >>= 1) acc += __shfl_xor_sync(0xffffffffu, acc, off);
        if (lane == 0) out[((size_t)b*C3 + o)*HW + y*96 + x] = acc;
    }
}

// ---------------- launch ----------------
extern "C" void kernel_launch(void* const* d_in, const int* in_sizes, int n_in,
                              void* d_out, int out_size) {
    const float* x     = (const float*)d_in[0];
    const float* w1    = (const float*)d_in[1];
    const float* f1ce  = (const float*)d_in[2];
    const float* f1gd  = (const float*)d_in[3];
    const float* f1gd2 = (const float*)d_in[4];
    const float* f1ci  = (const float*)d_in[5];
    const float* w2    = (const float*)d_in[6];
    const float* f2ce  = (const float*)d_in[7];
    const float* f2gd  = (const float*)d_in[8];
    const float* f2gd2 = (const float*)d_in[9];
    const float* f2ci  = (const float*)d_in[10];
    float* out = (float*)d_out;

    static int smem_set = 0;
    if (!smem_set) {
        cudaFuncSetAttribute(k6_fc2, cudaFuncAttributeMaxDynamicSharedMemorySize, 98304);
        smem_set = 1;
    }

    k0_zero<<<(B*194*128 + 255)/256, 256>>>();
    k1_gl1<<<B*C1, 256>>>(x);
    k2_dyn1<<<B, 256>>>(w1, f1ce, f1gd, f1gd2, f1ci);
    k3_fc1<<<dim3(HW/64, C2/64, B), 256>>>(x);
    k4_gl2<<<dim3(C2, B), 96>>>();
    k5a<<<B, 256>>>(f2ce, f2gd, f2gd2, f2ci);
    k5b<<<(B*9*C3*C2)/256, 256>>>(w2);
    k6_fc2<<<dim3(72, B), 256, 98304>>>(out);
    k7_edges<<<dim3(96, 2, B), 32>>>(out);
}